// round 4
// baseline (speedup 1.0000x reference)
#include <cuda_runtime.h>
#include <cuda_bf16.h>
#include <math.h>
#include <stdint.h>

// Problem constants
#define BB   128
#define NN   196
#define CC   768
#define HH   8
#define HD   96
#define MROWS (BB*NN)   // 25088
#define BHD   (BB*HH)   // 1024

// -------- device scratch (no runtime allocation allowed) --------
__device__ float g_Q[(size_t)MROWS*CC];
__device__ float g_K[(size_t)MROWS*CC];
__device__ float g_V[(size_t)MROWS*CC];
__device__ float g_A[(size_t)MROWS*CC];
__device__ float g_KV[(size_t)BHD*HD*HD];
__device__ float g_KS[(size_t)BHD*HD];
__device__ float g_invsc[CC];
__device__ float g_sa[MROWS];
__device__ float g_sa2[MROWS];
__device__ float g_sw[4*CC];
__device__ __align__(256) int8_t g_xqh[(size_t)MROWS*CC];
__device__ __align__(256) int8_t g_xql[(size_t)MROWS*CC];
__device__ __align__(256) int8_t g_aqh[(size_t)MROWS*CC];
__device__ __align__(256) int8_t g_aql[(size_t)MROWS*CC];
__device__ __align__(256) int8_t g_wqh[(size_t)4*CC*CC];
__device__ __align__(256) int8_t g_wql[(size_t)4*CC*CC];

// ======================= PTX helpers =======================
__device__ __forceinline__ uint32_t s2u(const void* p) {
    uint32_t a;
    asm("{ .reg .u64 t; cvta.to.shared.u64 t, %1; cvt.u32.u64 %0, t; }" : "=r"(a) : "l"(p));
    return a;
}

#define CP16(d, s) asm volatile("cp.async.cg.shared.global [%0], [%1], 16;" :: "r"(d), "l"(s))
#define CP_COMMIT() asm volatile("cp.async.commit_group;" ::: "memory")
#define CP_WAIT(n)  asm volatile("cp.async.wait_group %0;" :: "n"(n) : "memory")

#define LDSM4(r0, r1, r2, r3, a) \
    asm volatile("ldmatrix.sync.aligned.m8n8.x4.shared.b16 {%0,%1,%2,%3}, [%4];" \
        : "=r"(r0), "=r"(r1), "=r"(r2), "=r"(r3) : "r"(a))

#define IMMA(dp, a, b0, b1) \
    asm volatile("mma.sync.aligned.m16n8k32.row.col.s32.s8.s8.s32 " \
        "{%0,%1,%2,%3},{%4,%5,%6,%7},{%8,%9},{%0,%1,%2,%3};" \
        : "+r"((dp)[0]), "+r"((dp)[1]), "+r"((dp)[2]), "+r"((dp)[3]) \
        : "r"((a)[0]), "r"((a)[1]), "r"((a)[2]), "r"((a)[3]), "r"(b0), "r"(b1))

// smem swizzle for 64-byte rows: row r, 16B chunk c (0..3) -> byte offset
__device__ __forceinline__ uint32_t swoff(int r, int c) {
    return (uint32_t)(r * 64 + ((c ^ ((r >> 1) & 3)) << 4));
}

// ======================= int8 split GEMM (IMMA m16n8k32) =======================
// C[M,768] = A[M,768] @ W ; W^T stored [N][K] int8 hi/lo with per-n scale.
// A int8 hi/lo with per-row scale.  D = sa*sw*(HH + CROSS/128) + bias (+pos).
// CTA tile 128x128, warp tile 64x32, BK=64 int8, 4-stage cp.async pipeline.
#define GITERS 12
#define GSTG   4
#define STGB   32768
#define OAH    0
#define OAL    8192
#define OBH    16384
#define OBL    24576
#define SMEM_TOTAL_G (GSTG*STGB)  // 131072

__global__ __launch_bounds__(256, 1) void gemm_i8(
    const int8_t* __restrict__ Aqh, const int8_t* __restrict__ Aql,
    const int8_t* __restrict__ Bqh, const int8_t* __restrict__ Bql,
    const float* __restrict__ sa, const float* __restrict__ sw,
    const float* __restrict__ bias, const float* __restrict__ pos,
    float* __restrict__ C, int addPos)
{
    extern __shared__ char smem[];
    const uint32_t sb = s2u(smem);
    const int tid  = threadIdx.x;
    const int lane = tid & 31;
    const int wid  = tid >> 5;
    const int wm   = (wid & 1) * 64;
    const int wn   = (wid >> 1) * 32;
    const int bm   = blockIdx.y * 128;
    const int bn   = blockIdx.x * 128;

#define LOAD_STAGE(s, kit) do {                                               \
    int k0 = (kit) * 64;                                                      \
    uint32_t st = sb + (uint32_t)(s) * STGB;                                  \
    _Pragma("unroll")                                                         \
    for (int i = 0; i < 2; i++) {                                             \
        int u = i * 256 + tid; int r = u >> 2, c = u & 3;                     \
        uint32_t so = swoff(r, c);                                            \
        size_t ga = (size_t)(bm + r) * CC + k0 + c * 16;                      \
        size_t gb = (size_t)(bn + r) * CC + k0 + c * 16;                      \
        CP16(st + OAH + so, Aqh + ga);                                        \
        CP16(st + OAL + so, Aql + ga);                                        \
        CP16(st + OBH + so, Bqh + gb);                                        \
        CP16(st + OBL + so, Bql + gb);                                        \
    }                                                                         \
    CP_COMMIT();                                                              \
} while (0)

    int hh[4][4][4];
    int xx[4][4][4];
#pragma unroll
    for (int a = 0; a < 4; a++)
#pragma unroll
        for (int b = 0; b < 4; b++)
#pragma unroll
            for (int c = 0; c < 4; c++) { hh[a][b][c] = 0; xx[a][b][c] = 0; }

    LOAD_STAGE(0, 0);
    LOAD_STAGE(1, 1);
    LOAD_STAGE(2, 2);

    const int arow = lane & 15;
    const int achk = lane >> 4;
    const int brow = (lane & 7) + ((lane >> 4) & 1) * 8;
    const int bchk = (lane >> 3) & 1;

    for (int it = 0; it < GITERS; ++it) {
        int rem = GITERS - 1 - it;
        if (rem >= 2) { CP_WAIT(2); }
        else if (rem == 1) { CP_WAIT(1); }
        else { CP_WAIT(0); }
        __syncthreads();

        int ld = it + GSTG - 1;
        if (ld < GITERS) LOAD_STAGE(ld & 3, ld);

        uint32_t st = sb + (uint32_t)(it & 3) * STGB;
#pragma unroll
        for (int kk = 0; kk < 2; kk++) {
            uint32_t ah4[4][4], al4[4][4];
#pragma unroll
            for (int mt = 0; mt < 4; mt++) {
                int row = wm + mt * 16 + arow;
                uint32_t off = swoff(row, kk * 2 + achk);
                LDSM4(ah4[mt][0], ah4[mt][1], ah4[mt][2], ah4[mt][3], st + OAH + off);
                LDSM4(al4[mt][0], al4[mt][1], al4[mt][2], al4[mt][3], st + OAL + off);
            }
#pragma unroll
            for (int g = 0; g < 2; g++) {
                int row = wn + g * 16 + brow;
                uint32_t off = swoff(row, kk * 2 + bchk);
                uint32_t bh0, bh1, bh2, bh3, bl0, bl1, bl2, bl3;
                LDSM4(bh0, bh1, bh2, bh3, st + OBH + off);
                LDSM4(bl0, bl1, bl2, bl3, st + OBL + off);
#pragma unroll
                for (int mt = 0; mt < 4; mt++) {
                    IMMA(hh[mt][g * 2],     ah4[mt], bh0, bh1);
                    IMMA(xx[mt][g * 2],     ah4[mt], bl0, bl1);
                    IMMA(xx[mt][g * 2],     al4[mt], bh0, bh1);
                    IMMA(hh[mt][g * 2 + 1], ah4[mt], bh2, bh3);
                    IMMA(xx[mt][g * 2 + 1], ah4[mt], bl2, bl3);
                    IMMA(xx[mt][g * 2 + 1], al4[mt], bh2, bh3);
                }
            }
        }
    }

    // epilogue: dequant + bias (+pos)
#pragma unroll
    for (int mt = 0; mt < 4; mt++) {
#pragma unroll
        for (int i = 0; i < 2; i++) {
            int grow = bm + wm + mt * 16 + (lane >> 2) + i * 8;
            int prow = grow % NN;
            float fsa = sa[grow];
            float* crow = C + (size_t)grow * CC;
            const float* pr = pos + (size_t)prow * CC;
#pragma unroll
            for (int nq = 0; nq < 4; nq++) {
                int col = bn + wn + nq * 8 + (lane & 3) * 2;
                float2 w2 = *(const float2*)(sw + col);
                float v0 = (float)hh[mt][nq][i * 2]     + 0.0078125f * (float)xx[mt][nq][i * 2];
                float v1 = (float)hh[mt][nq][i * 2 + 1] + 0.0078125f * (float)xx[mt][nq][i * 2 + 1];
                float2 o;
                o.x = v0 * fsa * w2.x + bias[col];
                o.y = v1 * fsa * w2.y + bias[col + 1];
                if (addPos) {
                    o.x += pr[col];
                    o.y += pr[col + 1];
                }
                *(float2*)(crow + col) = o;
            }
        }
    }
#undef LOAD_STAGE
}

// ======================= activation int8 quantize (per row) =======================
__global__ __launch_bounds__(192) void xquant(
    const float4* __restrict__ A, char4* __restrict__ Qh, char4* __restrict__ Ql,
    float* __restrict__ sa)
{
    int row = blockIdx.x;
    int tid = threadIdx.x;
    float4 v = A[(size_t)row * 192 + tid];

    float m = fmaxf(fmaxf(fabsf(v.x), fabsf(v.y)), fmaxf(fabsf(v.z), fabsf(v.w)));
    __shared__ float red[6];
    unsigned lane = tid & 31, w = tid >> 5;
#pragma unroll
    for (int o = 16; o > 0; o >>= 1)
        m = fmaxf(m, __shfl_down_sync(0xffffffffu, m, o));
    if (lane == 0) red[w] = m;
    __syncthreads();
    float mx = red[0];
#pragma unroll
    for (int i = 1; i < 6; i++) mx = fmaxf(mx, red[i]);
    float s = fmaxf(mx, 1e-20f) * (1.0f / 126.0f);
    float inv = 126.0f / fmaxf(mx, 1e-20f);
    if (tid == 0) sa[row] = s;

    float q0 = v.x * inv, q1 = v.y * inv, q2 = v.z * inv, q3 = v.w * inv;
    float h0 = rintf(q0), h1 = rintf(q1), h2 = rintf(q2), h3 = rintf(q3);
    float l0 = rintf((q0 - h0) * 128.f), l1 = rintf((q1 - h1) * 128.f);
    float l2 = rintf((q2 - h2) * 128.f), l3 = rintf((q3 - h3) * 128.f);
    char4 ch, cl;
    ch.x = (char)(int)h0; ch.y = (char)(int)h1; ch.z = (char)(int)h2; ch.w = (char)(int)h3;
    cl.x = (char)(int)l0; cl.y = (char)(int)l1; cl.z = (char)(int)l2; cl.w = (char)(int)l3;
    Qh[(size_t)row * 192 + tid] = ch;
    Ql[(size_t)row * 192 + tid] = cl;
}

// ======================= weight scale (colmax of |W| per output n) =======================
__global__ __launch_bounds__(128) void wqmax(
    const float* __restrict__ W0, const float* __restrict__ W1,
    const float* __restrict__ W2, const float* __restrict__ W3,
    float* __restrict__ swall)
{
    const float* W = (blockIdx.z == 0) ? W0 : (blockIdx.z == 1) ? W1 :
                     (blockIdx.z == 2) ? W2 : W3;
    int n = blockIdx.x;
    int tid = threadIdx.x;
    float m = 0.f;
#pragma unroll
    for (int i = 0; i < 6; i++)
        m = fmaxf(m, fabsf(W[(size_t)(tid + i * 128) * CC + n]));
    __shared__ float red[4];
    unsigned lane = tid & 31, w = tid >> 5;
#pragma unroll
    for (int o = 16; o > 0; o >>= 1)
        m = fmaxf(m, __shfl_down_sync(0xffffffffu, m, o));
    if (lane == 0) red[w] = m;
    __syncthreads();
    if (tid == 0) {
        float mx = fmaxf(fmaxf(red[0], red[1]), fmaxf(red[2], red[3]));
        swall[blockIdx.z * CC + n] = fmaxf(mx, 1e-20f) * (1.0f / 126.0f);
    }
}

// ======================= weight transpose + int8 quantize =======================
__global__ void wquant(
    const float* __restrict__ W0, const float* __restrict__ W1,
    const float* __restrict__ W2, const float* __restrict__ W3,
    const float* __restrict__ swall,
    int8_t* __restrict__ Qh, int8_t* __restrict__ Ql)
{
    const float* W = (blockIdx.z == 0) ? W0 : (blockIdx.z == 1) ? W1 :
                     (blockIdx.z == 2) ? W2 : W3;
    size_t wo = (size_t)blockIdx.z * CC * CC;
    __shared__ float t[32][33];
    int n0 = blockIdx.x * 32, k0 = blockIdx.y * 32;
    int tx = threadIdx.x, ty = threadIdx.y;
#pragma unroll
    for (int i = 0; i < 4; i++)
        t[ty + 8 * i][tx] = W[(size_t)(k0 + ty + 8 * i) * CC + n0 + tx];
    __syncthreads();
#pragma unroll
    for (int i = 0; i < 4; i++) {
        int n = n0 + ty + 8 * i;
        float inv = 1.0f / swall[blockIdx.z * CC + n];
        float q = t[tx][ty + 8 * i] * inv;
        float h = rintf(q);
        float l = rintf((q - h) * 128.f);
        size_t o = wo + (size_t)n * CC + k0 + tx;
        Qh[o] = (char)(int)h;
        Ql[o] = (char)(int)l;
    }
}

// ======================= inv softplus precompute =======================
__global__ void invsp_kernel(const float* __restrict__ sp)
{
    int c = blockIdx.x * 256 + threadIdx.x;
    if (c < CC) {
        float s = sp[c];
        float v = (s > 20.f) ? s : log1pf(expf(s));
        g_invsc[c] = 1.0f / v;
    }
}

// ======================= focusing kernel (float4, 192 thr) =======================
__global__ __launch_bounds__(192) void focus_kernel(float* __restrict__ q, float* __restrict__ k)
{
    float* t = blockIdx.y ? k : q;
    float4* p = (float4*)(t + (size_t)blockIdx.x * CC);
    const int tid = threadIdx.x;

    float4 x = p[tid];
    const float4 iv = ((const float4*)g_invsc)[tid];

    float v0 = (fmaxf(x.x, 0.f) + 1e-6f) * iv.x;
    float v1 = (fmaxf(x.y, 0.f) + 1e-6f) * iv.y;
    float v2 = (fmaxf(x.z, 0.f) + 1e-6f) * iv.z;
    float v3 = (fmaxf(x.w, 0.f) + 1e-6f) * iv.w;

    float a0 = v0 * v0, a1 = v1 * v1, a2 = v2 * v2, a3 = v3 * v3;
    float s2 = a0 + a1 + a2 + a3;
    float c0 = a0 * v0, c1 = a1 * v1, c2 = a2 * v2, c3 = a3 * v3;
    float s6 = c0 * c0 + c1 * c1 + c2 * c2 + c3 * c3;

    __shared__ float red2[6], red6[6];
    unsigned lane = tid & 31, w = tid >> 5;
#pragma unroll
    for (int o = 16; o > 0; o >>= 1) {
        s2 += __shfl_down_sync(0xffffffffu, s2, o);
        s6 += __shfl_down_sync(0xffffffffu, s6, o);
    }
    if (lane == 0) { red2[w] = s2; red6[w] = s6; }
    __syncthreads();
    float t2 = 0.f, t6 = 0.f;
#pragma unroll
    for (int i = 0; i < 6; i++) { t2 += red2[i]; t6 += red6[i]; }
    float f = sqrtf(t2 / t6);

    float4 o4;
    o4.x = c0 * f; o4.y = c1 * f; o4.z = c2 * f; o4.w = c3 * f;
    p[tid] = o4;
}

// ======================= ksum =======================
__global__ void ksum_kernel(const float* __restrict__ k, float* __restrict__ ksum)
{
    int bh = blockIdx.x;
    int b = bh >> 3, h = bh & 7;
    int c = threadIdx.x;
    const float* base = k + (size_t)b * NN * CC + h * HD + c;
    float s = 0.f;
#pragma unroll 4
    for (int j = 0; j < NN; j++) s += base[(size_t)j * CC];
    ksum[bh * HD + c] = s;
}

// ======================= kv = k^T v per (b,h) =======================
__global__ __launch_bounds__(256) void kv_kernel(
    const float* __restrict__ k, const float* __restrict__ v, float* __restrict__ kv)
{
    int bh = blockIdx.x;
    int b = bh >> 3, h = bh & 7;
    __shared__ float ks[28][HD];
    __shared__ float vs[28][HD];
    const int tid = threadIdx.x;
    const int ty = tid >> 4;
    const int tx = tid & 15;

    float acc[6][6];
#pragma unroll
    for (int i = 0; i < 6; i++)
#pragma unroll
        for (int j = 0; j < 6; j++) acc[i][j] = 0.f;

    const float* kb = k + (size_t)b * NN * CC + h * HD;
    const float* vb = v + (size_t)b * NN * CC + h * HD;

    for (int j0 = 0; j0 < NN; j0 += 28) {
        for (int idx = tid; idx < 28 * HD; idx += 256) {
            int j = idx / HD, c = idx % HD;
            ks[j][c] = kb[(size_t)(j0 + j) * CC + c];
            vs[j][c] = vb[(size_t)(j0 + j) * CC + c];
        }
        __syncthreads();
#pragma unroll 7
        for (int j = 0; j < 28; j++) {
            float kf[6], vf[6];
#pragma unroll
            for (int i = 0; i < 6; i++) kf[i] = ks[j][ty * 6 + i];
#pragma unroll
            for (int i = 0; i < 6; i++) vf[i] = vs[j][tx * 6 + i];
#pragma unroll
            for (int i = 0; i < 6; i++)
#pragma unroll
                for (int l = 0; l < 6; l++)
                    acc[i][l] = fmaf(kf[i], vf[l], acc[i][l]);
        }
        __syncthreads();
    }

#pragma unroll
    for (int i = 0; i < 6; i++)
#pragma unroll
        for (int l = 0; l < 6; l++)
            kv[(size_t)bh * HD * HD + (ty * 6 + i) * HD + tx * 6 + l] = acc[i][l];
}

// ======================= attention output (z fused) =======================
__global__ __launch_bounds__(224) void attnout_kernel(
    const float* __restrict__ q, const float* __restrict__ kv,
    const float* __restrict__ ksum, float* __restrict__ outb)
{
    int bh = blockIdx.x;
    int b = bh >> 3, h = bh & 7;
    __shared__ __align__(16) float kvs[HD * HD];
    __shared__ float ksm[HD];
    const int tid = threadIdx.x;

    for (int idx = tid; idx < HD * HD; idx += 224)
        kvs[idx] = kv[(size_t)bh * HD * HD + idx];
    if (tid < HD) ksm[tid] = ksum[bh * HD + tid];
    __syncthreads();

    if (tid < NN) {
        const float* qr = q + ((size_t)b * NN + tid) * CC + h * HD;
        float zi = 0.f;
#pragma unroll 8
        for (int c = 0; c < HD; c++) zi += qr[c] * ksm[c];
        zi = 1.f / (zi + 1e-6f);

        float4 acc[24];
#pragma unroll
        for (int d = 0; d < 24; d++) acc[d] = make_float4(0.f, 0.f, 0.f, 0.f);

        for (int c = 0; c < HD; c++) {
            float qv = qr[c];
            const float4* kr = (const float4*)(kvs + c * HD);
#pragma unroll
            for (int d = 0; d < 24; d++) {
                float4 k4 = kr[d];
                acc[d].x = fmaf(qv, k4.x, acc[d].x);
                acc[d].y = fmaf(qv, k4.y, acc[d].y);
                acc[d].z = fmaf(qv, k4.z, acc[d].z);
                acc[d].w = fmaf(qv, k4.w, acc[d].w);
            }
        }

        float* orow = outb + ((size_t)b * NN + tid) * CC + h * HD;
#pragma unroll
        for (int d = 0; d < 24; d++) {
            float4 r = acc[d];
            r.x *= zi; r.y *= zi; r.z *= zi; r.w *= zi;
            *(float4*)(orow + d * 4) = r;
        }
    }
}

// ======================= depthwise 5x5 conv on v (14x14) =======================
__global__ __launch_bounds__(224) void dwc_kernel(
    const float* __restrict__ v, const float* __restrict__ w,
    const float* __restrict__ bias, float* __restrict__ outb)
{
    int bh = blockIdx.x;
    int b = bh >> 3, h = bh & 7;
    int c0 = blockIdx.y * 48;

    __shared__ float vs[NN * 49];
    __shared__ float ws[48 * 25];
    __shared__ float bs[48];
    const int tid = threadIdx.x;

    for (int idx = tid; idx < NN * 48; idx += 224) {
        int p = idx / 48, c = idx % 48;
        vs[p * 49 + c] = v[((size_t)b * NN + p) * CC + h * HD + c0 + c];
    }
    for (int idx = tid; idx < 48 * 25; idx += 224) ws[idx] = w[c0 * 25 + idx];
    if (tid < 48) bs[tid] = bias[c0 + tid];
    __syncthreads();

    if (tid < NN) {
        int y = tid / 14, x = tid % 14;
        float* orow = outb + ((size_t)b * NN + tid) * CC + h * HD + c0;
        for (int c = 0; c < 48; c++) {
            float s = bs[c];
#pragma unroll
            for (int dy = -2; dy <= 2; dy++) {
                int yy = y + dy;
                if ((unsigned)yy >= 14u) continue;
#pragma unroll
                for (int dx = -2; dx <= 2; dx++) {
                    int xx = x + dx;
                    if ((unsigned)xx >= 14u) continue;
                    s = fmaf(ws[c * 25 + (dy + 2) * 5 + (dx + 2)],
                             vs[(yy * 14 + xx) * 49 + c], s);
                }
            }
            orow[c] += s;
        }
    }
}

// ======================= launch =======================
extern "C" void kernel_launch(void* const* d_in, const int* in_sizes, int n_in,
                              void* d_out, int out_size)
{
    const float* x   = (const float*)d_in[0];
    const float* Wq  = (const float*)d_in[1];
    const float* bq  = (const float*)d_in[2];
    const float* Wk  = (const float*)d_in[3];
    const float* bk  = (const float*)d_in[4];
    const float* Wv  = (const float*)d_in[5];
    const float* bv  = (const float*)d_in[6];
    const float* pos = (const float*)d_in[7];
    const float* sp  = (const float*)d_in[8];
    const float* dw  = (const float*)d_in[9];
    const float* db  = (const float*)d_in[10];
    const float* Wp  = (const float*)d_in[11];
    const float* bp  = (const float*)d_in[12];
    float* out = (float*)d_out;

    float *Q, *K, *V, *Ab, *KV, *KS, *sa, *sa2, *sw;
    int8_t *xqh, *xql, *aqh, *aql, *wqh, *wql;
    cudaGetSymbolAddress((void**)&Q,   g_Q);
    cudaGetSymbolAddress((void**)&K,   g_K);
    cudaGetSymbolAddress((void**)&V,   g_V);
    cudaGetSymbolAddress((void**)&Ab,  g_A);
    cudaGetSymbolAddress((void**)&KV,  g_KV);
    cudaGetSymbolAddress((void**)&KS,  g_KS);
    cudaGetSymbolAddress((void**)&sa,  g_sa);
    cudaGetSymbolAddress((void**)&sa2, g_sa2);
    cudaGetSymbolAddress((void**)&sw,  g_sw);
    cudaGetSymbolAddress((void**)&xqh, g_xqh);
    cudaGetSymbolAddress((void**)&xql, g_xql);
    cudaGetSymbolAddress((void**)&aqh, g_aqh);
    cudaGetSymbolAddress((void**)&aql, g_aql);
    cudaGetSymbolAddress((void**)&wqh, g_wqh);
    cudaGetSymbolAddress((void**)&wql, g_wql);

    cudaFuncSetAttribute(gemm_i8, cudaFuncAttributeMaxDynamicSharedMemorySize, SMEM_TOTAL_G);

    const size_t WSZ = (size_t)CC * CC;

    // 0: weight scales
    wqmax<<<dim3(CC, 1, 4), 128>>>(Wq, Wk, Wv, Wp, sw);
    // 1: weight transpose + quantize
    wquant<<<dim3(24, 24, 4), dim3(32, 8)>>>(Wq, Wk, Wv, Wp, sw, wqh, wql);
    // 2: activation quantize
    xquant<<<MROWS, 192>>>((const float4*)x, (char4*)xqh, (char4*)xql, sa);
    // 3: softplus reciprocal
    invsp_kernel<<<3, 256>>>(sp);

    dim3 gg(CC / 128, MROWS / 128);   // (6, 196)
    // 4,5,6: Q,K,V projections (ncu -s 5 lands on K GEMM)
    gemm_i8<<<gg, 256, SMEM_TOTAL_G>>>(xqh, xql, wqh + 0 * WSZ, wql + 0 * WSZ, sa, sw + 0 * CC, bq, pos, Q, 0);
    gemm_i8<<<gg, 256, SMEM_TOTAL_G>>>(xqh, xql, wqh + 1 * WSZ, wql + 1 * WSZ, sa, sw + 1 * CC, bk, pos, K, 1);
    gemm_i8<<<gg, 256, SMEM_TOTAL_G>>>(xqh, xql, wqh + 2 * WSZ, wql + 2 * WSZ, sa, sw + 2 * CC, bv, pos, V, 0);

    // 7: focusing
    focus_kernel<<<dim3(MROWS, 2), 192>>>(Q, K);

    // 8-11: linear attention + dwc
    ksum_kernel<<<BHD, HD>>>(K, KS);
    kv_kernel<<<BHD, 256>>>(K, V, KV);
    attnout_kernel<<<BHD, 224>>>(Q, KV, KS, Ab);
    dwc_kernel<<<dim3(BHD, 2), 224>>>(V, dw, db, Ab);

    // 12: quantize attention output, 13: output projection
    xquant<<<MROWS, 192>>>((const float4*)Ab, (char4*)aqh, (char4*)aql, sa2);
    gemm_i8<<<gg, 256, SMEM_TOTAL_G>>>(aqh, aql, wqh + 3 * WSZ, wql + 3 * WSZ, sa2, sw + 3 * CC, bp, pos, out, 0);
}

// round 5
// speedup vs baseline: 2.2248x; 2.2248x over previous
#include <cuda_runtime.h>
#include <cuda_fp16.h>
#include <math.h>
#include <stdint.h>

// Problem constants
#define BB   128
#define NN   196
#define CC   768
#define HH   8
#define HD   96
#define MROWS (BB*NN)   // 25088
#define BHD   (BB*HH)   // 1024

// -------- device scratch (no runtime allocation allowed) --------
__device__ float g_Q[(size_t)MROWS*CC];
__device__ float g_K[(size_t)MROWS*CC];
__device__ float g_V[(size_t)MROWS*CC];
__device__ float g_A[(size_t)MROWS*CC];
__device__ float g_KV[(size_t)BHD*HD*HD];
__device__ float g_KS[(size_t)BHD*HD];
__device__ float g_invsc[CC];
__device__ __half g_xh[(size_t)MROWS*CC];
__device__ __half g_xl[(size_t)MROWS*CC];
__device__ __half g_ah[(size_t)MROWS*CC];
__device__ __half g_al[(size_t)MROWS*CC];
__device__ __half g_wh[(size_t)4*CC*CC];
__device__ __half g_wl[(size_t)4*CC*CC];

// ======================= PTX helpers =======================
__device__ __forceinline__ uint32_t s2u(const void* p) {
    uint32_t a;
    asm("{ .reg .u64 t; cvta.to.shared.u64 t, %1; cvt.u32.u64 %0, t; }" : "=r"(a) : "l"(p));
    return a;
}

#define CP16(d, s) asm volatile("cp.async.cg.shared.global [%0], [%1], 16;" :: "r"(d), "l"(s))
#define CP_COMMIT() asm volatile("cp.async.commit_group;" ::: "memory")
#define CP_WAIT(n)  asm volatile("cp.async.wait_group %0;" :: "n"(n) : "memory")

#define LDSM4(r0, r1, r2, r3, a) \
    asm volatile("ldmatrix.sync.aligned.m8n8.x4.shared.b16 {%0,%1,%2,%3}, [%4];" \
        : "=r"(r0), "=r"(r1), "=r"(r2), "=r"(r3) : "r"(a))

#define MMA(dp, a, b0, b1) \
    asm volatile("mma.sync.aligned.m16n8k16.row.col.f32.f16.f16.f32 " \
        "{%0,%1,%2,%3},{%4,%5,%6,%7},{%8,%9},{%0,%1,%2,%3};" \
        : "+f"((dp)[0]), "+f"((dp)[1]), "+f"((dp)[2]), "+f"((dp)[3]) \
        : "r"((a)[0]), "r"((a)[1]), "r"((a)[2]), "r"((a)[3]), "r"(b0), "r"(b1))

// smem chunk swizzle: element row r, 16B chunk c (0..3) -> byte offset
__device__ __forceinline__ uint32_t swoff(int r, int c) {
    return (uint32_t)(r * 64 + ((c ^ ((r >> 1) & 3)) << 4));
}

// ======================= split-fp16 mma.sync GEMM =======================
// C[M,768] = A[M,768] @ W ; W^T stored [N][K] K-contiguous, split hi/lo fp16.
// NT=3: Ah*Bh + Ah*Bl + Al*Bh.  NT=2: Ah*Bh + Ah*Bl (A single fp16).
// CTA tile 128x256, warp tile 64x64, BK=32, 4-stage cp.async pipeline.
#define GITERS 24
#define GSTG   4
#define STGB   49152
#define OAH    0
#define OAL    8192
#define OBH    16384
#define OBL    32768
#define SMEM_TOTAL_G (GSTG*STGB)  // 196608

template<int NT>
__global__ __launch_bounds__(256, 1) void gemm_f16(
    const __half* __restrict__ Ah, const __half* __restrict__ Al,
    const __half* __restrict__ Bh, const __half* __restrict__ Bl,
    const float* __restrict__ bias, const float* __restrict__ pos,
    float* __restrict__ C, int addPos)
{
    extern __shared__ char smem[];
    const uint32_t sb = s2u(smem);
    const int tid  = threadIdx.x;
    const int lane = tid & 31;
    const int wid  = tid >> 5;
    const int wm   = (wid & 1) * 64;
    const int wn   = (wid >> 1) * 64;
    const int bm   = blockIdx.y * 128;
    const int bn   = blockIdx.x * 256;

#define LOAD_STAGE(s, kit) do {                                               \
    int k0 = (kit) * 32;                                                      \
    uint32_t st = sb + (uint32_t)(s) * STGB;                                  \
    _Pragma("unroll")                                                         \
    for (int i = 0; i < 2; i++) {                                             \
        int u = i * 256 + tid; int r = u >> 2, c = u & 3;                     \
        uint32_t so = swoff(r, c);                                            \
        size_t go = (size_t)(bm + r) * CC + k0 + c * 8;                       \
        CP16(st + OAH + so, Ah + go);                                         \
        if (NT == 3) CP16(st + OAL + so, Al + go);                            \
    }                                                                         \
    _Pragma("unroll")                                                         \
    for (int i = 0; i < 4; i++) {                                             \
        int u = i * 256 + tid; int r = u >> 2, c = u & 3;                     \
        uint32_t so = swoff(r, c);                                            \
        size_t go = (size_t)(bn + r) * CC + k0 + c * 8;                       \
        CP16(st + OBH + so, Bh + go);                                         \
        CP16(st + OBL + so, Bl + go);                                         \
    }                                                                         \
    CP_COMMIT();                                                              \
} while (0)

    float acc[4][8][4];
#pragma unroll
    for (int a = 0; a < 4; a++)
#pragma unroll
        for (int b = 0; b < 8; b++)
#pragma unroll
            for (int c = 0; c < 4; c++) acc[a][b][c] = 0.f;

    LOAD_STAGE(0, 0);
    LOAD_STAGE(1, 1);
    LOAD_STAGE(2, 2);

    const int arow = lane & 15;
    const int achk = lane >> 4;
    const int brow = (lane & 7) + ((lane >> 4) & 1) * 8;
    const int bchk = (lane >> 3) & 1;

    for (int it = 0; it < GITERS; ++it) {
        int rem = GITERS - 1 - it;
        if (rem >= 2) { CP_WAIT(2); }
        else if (rem == 1) { CP_WAIT(1); }
        else { CP_WAIT(0); }
        __syncthreads();

        int ld = it + GSTG - 1;
        if (ld < GITERS) LOAD_STAGE(ld & 3, ld);

        uint32_t st = sb + (uint32_t)(it & 3) * STGB;
#pragma unroll
        for (int kk = 0; kk < 2; kk++) {
            uint32_t ahf[4][4], alf[4][4];
#pragma unroll
            for (int mt = 0; mt < 4; mt++) {
                int row = wm + mt * 16 + arow;
                uint32_t off = swoff(row, kk * 2 + achk);
                LDSM4(ahf[mt][0], ahf[mt][1], ahf[mt][2], ahf[mt][3], st + OAH + off);
                if (NT == 3)
                    LDSM4(alf[mt][0], alf[mt][1], alf[mt][2], alf[mt][3], st + OAL + off);
            }
#pragma unroll
            for (int bq = 0; bq < 4; bq++) {
                int row = wn + bq * 16 + brow;
                uint32_t off = swoff(row, kk * 2 + bchk);
                uint32_t bh0, bh1, bh2, bh3, bl0, bl1, bl2, bl3;
                LDSM4(bh0, bh1, bh2, bh3, st + OBH + off);
                LDSM4(bl0, bl1, bl2, bl3, st + OBL + off);
#pragma unroll
                for (int mt = 0; mt < 4; mt++) {
                    MMA(acc[mt][bq * 2],     ahf[mt], bh0, bh1);
                    MMA(acc[mt][bq * 2],     ahf[mt], bl0, bl1);
                    if (NT == 3)
                        MMA(acc[mt][bq * 2], alf[mt], bh0, bh1);
                    MMA(acc[mt][bq * 2 + 1], ahf[mt], bh2, bh3);
                    MMA(acc[mt][bq * 2 + 1], ahf[mt], bl2, bl3);
                    if (NT == 3)
                        MMA(acc[mt][bq * 2 + 1], alf[mt], bh2, bh3);
                }
            }
        }
    }

    // epilogue: write acc + bias (+pos)
#pragma unroll
    for (int mt = 0; mt < 4; mt++) {
#pragma unroll
        for (int i = 0; i < 2; i++) {
            int grow = bm + wm + mt * 16 + (lane >> 2) + i * 8;
            int prow = grow % NN;
            float* crow = C + (size_t)grow * CC;
            const float* pr = pos + (size_t)prow * CC;
#pragma unroll
            for (int nq = 0; nq < 8; nq++) {
                int col = bn + wn + nq * 8 + (lane & 3) * 2;
                float2 o;
                o.x = acc[mt][nq][i * 2]     + bias[col];
                o.y = acc[mt][nq][i * 2 + 1] + bias[col + 1];
                if (addPos) {
                    o.x += pr[col];
                    o.y += pr[col + 1];
                }
                *(float2*)(crow + col) = o;
            }
        }
    }
#undef LOAD_STAGE
}

// ======================= weight transpose + fp16 split (all 4 weights) ===
__global__ void wsplit_kernel(
    const float* __restrict__ W0, const float* __restrict__ W1,
    const float* __restrict__ W2, const float* __restrict__ W3,
    __half* __restrict__ Wh, __half* __restrict__ Wl)
{
    const float* W = (blockIdx.z == 0) ? W0 : (blockIdx.z == 1) ? W1 :
                     (blockIdx.z == 2) ? W2 : W3;
    size_t wo = (size_t)blockIdx.z * CC * CC;
    __shared__ float t[32][33];
    int n0 = blockIdx.x * 32, k0 = blockIdx.y * 32;
    int tx = threadIdx.x, ty = threadIdx.y;
#pragma unroll
    for (int i = 0; i < 4; i++)
        t[ty + 8 * i][tx] = W[(size_t)(k0 + ty + 8 * i) * CC + n0 + tx];
    __syncthreads();
#pragma unroll
    for (int i = 0; i < 4; i++) {
        float a = t[tx][ty + 8 * i];
        __half h = __float2half_rn(a);
        __half l = __float2half_rn(a - __half2float(h));
        size_t o = wo + (size_t)(n0 + ty + 8 * i) * CC + k0 + tx;
        Wh[o] = h; Wl[o] = l;
    }
}

// ======================= activation fp16 split =======================
__global__ __launch_bounds__(256) void split_kernel(
    const float4* __restrict__ A, __half2* __restrict__ Ah,
    __half2* __restrict__ Al, int n4)
{
    int i = blockIdx.x * 256 + threadIdx.x;
    if (i < n4) {
        float4 a = A[i];
        __half h0 = __float2half_rn(a.x);
        __half h1 = __float2half_rn(a.y);
        __half h2 = __float2half_rn(a.z);
        __half h3 = __float2half_rn(a.w);
        __half l0 = __float2half_rn(a.x - __half2float(h0));
        __half l1 = __float2half_rn(a.y - __half2float(h1));
        __half l2 = __float2half_rn(a.z - __half2float(h2));
        __half l3 = __float2half_rn(a.w - __half2float(h3));
        Ah[2 * i]     = __half2{h0, h1};
        Ah[2 * i + 1] = __half2{h2, h3};
        Al[2 * i]     = __half2{l0, l1};
        Al[2 * i + 1] = __half2{l2, l3};
    }
}

// ======================= inv softplus precompute =======================
__global__ void invsp_kernel(const float* __restrict__ sp)
{
    int c = blockIdx.x * 256 + threadIdx.x;
    if (c < CC) {
        float s = sp[c];
        float v = (s > 20.f) ? s : log1pf(expf(s));
        g_invsc[c] = 1.0f / v;
    }
}

// ======================= focusing kernel (float4, 192 thr) =======================
__global__ __launch_bounds__(192) void focus_kernel(float* __restrict__ q, float* __restrict__ k)
{
    float* t = blockIdx.y ? k : q;
    float4* p = (float4*)(t + (size_t)blockIdx.x * CC);
    const int tid = threadIdx.x;

    float4 x = p[tid];
    const float4 iv = ((const float4*)g_invsc)[tid];

    float v0 = (fmaxf(x.x, 0.f) + 1e-6f) * iv.x;
    float v1 = (fmaxf(x.y, 0.f) + 1e-6f) * iv.y;
    float v2 = (fmaxf(x.z, 0.f) + 1e-6f) * iv.z;
    float v3 = (fmaxf(x.w, 0.f) + 1e-6f) * iv.w;

    float a0 = v0 * v0, a1 = v1 * v1, a2 = v2 * v2, a3 = v3 * v3;
    float s2 = a0 + a1 + a2 + a3;
    float c0 = a0 * v0, c1 = a1 * v1, c2 = a2 * v2, c3 = a3 * v3;
    float s6 = c0 * c0 + c1 * c1 + c2 * c2 + c3 * c3;

    __shared__ float red2[6], red6[6];
    unsigned lane = tid & 31, w = tid >> 5;
#pragma unroll
    for (int o = 16; o > 0; o >>= 1) {
        s2 += __shfl_down_sync(0xffffffffu, s2, o);
        s6 += __shfl_down_sync(0xffffffffu, s6, o);
    }
    if (lane == 0) { red2[w] = s2; red6[w] = s6; }
    __syncthreads();
    float t2 = 0.f, t6 = 0.f;
#pragma unroll
    for (int i = 0; i < 6; i++) { t2 += red2[i]; t6 += red6[i]; }
    float f = sqrtf(t2 / t6);

    float4 o4;
    o4.x = c0 * f; o4.y = c1 * f; o4.z = c2 * f; o4.w = c3 * f;
    p[tid] = o4;
}

// ======================= kv = k^T v per (b,h), ksum fused =======================
__global__ __launch_bounds__(256) void kv_kernel(
    const float* __restrict__ k, const float* __restrict__ v,
    float* __restrict__ kv, float* __restrict__ ksum)
{
    int bh = blockIdx.x;
    int b = bh >> 3, h = bh & 7;
    __shared__ float ks[28][HD];
    __shared__ float vs[28][HD];
    const int tid = threadIdx.x;
    const int ty = tid >> 4;
    const int tx = tid & 15;

    float acc[6][6];
    float cs[6];
#pragma unroll
    for (int i = 0; i < 6; i++) {
        cs[i] = 0.f;
#pragma unroll
        for (int j = 0; j < 6; j++) acc[i][j] = 0.f;
    }

    const float* kb = k + (size_t)b * NN * CC + h * HD;
    const float* vb = v + (size_t)b * NN * CC + h * HD;

    for (int j0 = 0; j0 < NN; j0 += 28) {
        for (int idx = tid; idx < 28 * HD; idx += 256) {
            int j = idx / HD, c = idx % HD;
            ks[j][c] = kb[(size_t)(j0 + j) * CC + c];
            vs[j][c] = vb[(size_t)(j0 + j) * CC + c];
        }
        __syncthreads();
#pragma unroll 7
        for (int j = 0; j < 28; j++) {
            float kf[6], vf[6];
#pragma unroll
            for (int i = 0; i < 6; i++) kf[i] = ks[j][ty * 6 + i];
#pragma unroll
            for (int i = 0; i < 6; i++) vf[i] = vs[j][tx * 6 + i];
            if (tx == 0) {
#pragma unroll
                for (int i = 0; i < 6; i++) cs[i] += kf[i];
            }
#pragma unroll
            for (int i = 0; i < 6; i++)
#pragma unroll
                for (int l = 0; l < 6; l++)
                    acc[i][l] = fmaf(kf[i], vf[l], acc[i][l]);
        }
        __syncthreads();
    }

#pragma unroll
    for (int i = 0; i < 6; i++)
#pragma unroll
        for (int l = 0; l < 6; l++)
            kv[(size_t)bh * HD * HD + (ty * 6 + i) * HD + tx * 6 + l] = acc[i][l];
    if (tx == 0) {
#pragma unroll
        for (int i = 0; i < 6; i++)
            ksum[bh * HD + ty * 6 + i] = cs[i];
    }
}

// ======================= fused attention output + depthwise conv ==========
// out[i][c] = zi * sum_c' q[i][c']*kv[c'][c]  +  dwc(v)[i][c] + dwc_bias[c]
#define SM_KV   0
#define SM_KSM  (HD*HD)
#define SM_WS   (SM_KSM + HD)
#define SM_BS   (SM_WS + HD*25)
#define SM_VS   (SM_BS + HD)
#define SMEM_AD ((SM_VS + NN*97) * 4)   // floats -> bytes

__global__ __launch_bounds__(224) void attn_dwc_kernel(
    const float* __restrict__ q, const float* __restrict__ kv,
    const float* __restrict__ ksum, const float* __restrict__ v,
    const float* __restrict__ w, const float* __restrict__ db,
    float* __restrict__ outb)
{
    extern __shared__ float sm[];
    int bh = blockIdx.x;
    int b = bh >> 3, h = bh & 7;
    const int tid = threadIdx.x;

    for (int idx = tid; idx < HD * HD; idx += 224)
        sm[SM_KV + idx] = kv[(size_t)bh * HD * HD + idx];
    for (int idx = tid; idx < NN * HD; idx += 224) {
        int p = idx / HD, c = idx % HD;
        sm[SM_VS + p * 97 + c] = v[((size_t)b * NN + p) * CC + h * HD + c];
    }
    for (int idx = tid; idx < HD * 25; idx += 224)
        sm[SM_WS + idx] = w[idx];
    if (tid < HD) {
        sm[SM_KSM + tid] = ksum[bh * HD + tid];
        sm[SM_BS + tid] = db[tid];
    }
    __syncthreads();

    if (tid < NN) {
        const float* qr = q + ((size_t)b * NN + tid) * CC + h * HD;
        float zi = 0.f;
#pragma unroll 8
        for (int c = 0; c < HD; c++) zi += qr[c] * sm[SM_KSM + c];
        zi = 1.f / (zi + 1e-6f);

        float4 acc[24];
#pragma unroll
        for (int d = 0; d < 24; d++) acc[d] = make_float4(0.f, 0.f, 0.f, 0.f);

        for (int c = 0; c < HD; c++) {
            float qv = qr[c];
            const float4* kr = (const float4*)(sm + SM_KV + c * HD);
#pragma unroll
            for (int d = 0; d < 24; d++) {
                float4 k4 = kr[d];
                acc[d].x = fmaf(qv, k4.x, acc[d].x);
                acc[d].y = fmaf(qv, k4.y, acc[d].y);
                acc[d].z = fmaf(qv, k4.z, acc[d].z);
                acc[d].w = fmaf(qv, k4.w, acc[d].w);
            }
        }

        const int y = tid / 14, x = tid % 14;
        float* orow = outb + ((size_t)b * NN + tid) * CC + h * HD;
#pragma unroll
        for (int d = 0; d < 24; d++) {
            float4 r = acc[d];
            r.x *= zi; r.y *= zi; r.z *= zi; r.w *= zi;
            float* rp = (float*)&r;
#pragma unroll
            for (int e = 0; e < 4; e++) {
                int c = d * 4 + e;
                float s = sm[SM_BS + c];
#pragma unroll
                for (int dy = -2; dy <= 2; dy++) {
                    int yy = y + dy;
                    if ((unsigned)yy >= 14u) continue;
#pragma unroll
                    for (int dx = -2; dx <= 2; dx++) {
                        int xx = x + dx;
                        if ((unsigned)xx >= 14u) continue;
                        s = fmaf(sm[SM_WS + c * 25 + (dy + 2) * 5 + (dx + 2)],
                                 sm[SM_VS + (yy * 14 + xx) * 97 + c], s);
                    }
                }
                rp[e] += s;
            }
            *(float4*)(orow + d * 4) = r;
        }
    }
}

// ======================= launch =======================
extern "C" void kernel_launch(void* const* d_in, const int* in_sizes, int n_in,
                              void* d_out, int out_size)
{
    const float* x   = (const float*)d_in[0];
    const float* Wq  = (const float*)d_in[1];
    const float* bq  = (const float*)d_in[2];
    const float* Wk  = (const float*)d_in[3];
    const float* bk  = (const float*)d_in[4];
    const float* Wv  = (const float*)d_in[5];
    const float* bv  = (const float*)d_in[6];
    const float* pos = (const float*)d_in[7];
    const float* sp  = (const float*)d_in[8];
    const float* dw  = (const float*)d_in[9];
    const float* db  = (const float*)d_in[10];
    const float* Wp  = (const float*)d_in[11];
    const float* bp  = (const float*)d_in[12];
    float* out = (float*)d_out;

    float *Q, *K, *V, *Ab, *KV, *KS;
    __half *xh, *xl, *ah, *al, *wh, *wl;
    cudaGetSymbolAddress((void**)&Q,  g_Q);
    cudaGetSymbolAddress((void**)&K,  g_K);
    cudaGetSymbolAddress((void**)&V,  g_V);
    cudaGetSymbolAddress((void**)&Ab, g_A);
    cudaGetSymbolAddress((void**)&KV, g_KV);
    cudaGetSymbolAddress((void**)&KS, g_KS);
    cudaGetSymbolAddress((void**)&xh, g_xh);
    cudaGetSymbolAddress((void**)&xl, g_xl);
    cudaGetSymbolAddress((void**)&ah, g_ah);
    cudaGetSymbolAddress((void**)&al, g_al);
    cudaGetSymbolAddress((void**)&wh, g_wh);
    cudaGetSymbolAddress((void**)&wl, g_wl);

    cudaFuncSetAttribute(gemm_f16<3>, cudaFuncAttributeMaxDynamicSharedMemorySize, SMEM_TOTAL_G);
    cudaFuncSetAttribute(gemm_f16<2>, cudaFuncAttributeMaxDynamicSharedMemorySize, SMEM_TOTAL_G);
    cudaFuncSetAttribute(attn_dwc_kernel, cudaFuncAttributeMaxDynamicSharedMemorySize, SMEM_AD);

    const size_t WSZ = (size_t)CC * CC;
    const int n4 = MROWS * CC / 4;

    // 0: weight transpose + split (all 4)
    wsplit_kernel<<<dim3(24, 24, 4), dim3(32, 8)>>>(Wq, Wk, Wv, Wp, wh, wl);
    // 1: x split
    split_kernel<<<(n4 + 255) / 256, 256>>>((const float4*)x,
        (__half2*)xh, (__half2*)xl, n4);
    // 2: softplus reciprocal
    invsp_kernel<<<3, 256>>>(sp);

    dim3 gg(CC / 256, MROWS / 128);   // (3, 196)
    // 3: V (2-term), 4: Q (3-term), 5: K (3-term; ncu -s 5 lands here)
    gemm_f16<2><<<gg, 256, SMEM_TOTAL_G>>>(xh, xl, wh + 2 * WSZ, wl + 2 * WSZ, bv, pos, V, 0);
    gemm_f16<3><<<gg, 256, SMEM_TOTAL_G>>>(xh, xl, wh + 0 * WSZ, wl + 0 * WSZ, bq, pos, Q, 0);
    gemm_f16<3><<<gg, 256, SMEM_TOTAL_G>>>(xh, xl, wh + 1 * WSZ, wl + 1 * WSZ, bk, pos, K, 1);

    // 6: focusing
    focus_kernel<<<dim3(MROWS, 2), 192>>>(Q, K);

    // 7: kv + ksum, 8: fused attention-out + dwc
    kv_kernel<<<BHD, 256>>>(K, V, KV, KS);
    attn_dwc_kernel<<<BHD, 224, SMEM_AD>>>(Q, KV, KS, V, dw, db, Ab);

    // 9: quantize attention output, 10: output projection (2-term)
    split_kernel<<<(n4 + 255) / 256, 256>>>((const float4*)Ab,
        (__half2*)ah, (__half2*)al, n4);
    gemm_f16<2><<<gg, 256, SMEM_TOTAL_G>>>(ah, al, wh + 3 * WSZ, wl + 3 * WSZ, bp, pos, out, 0);
}